// round 3
// baseline (speedup 1.0000x reference)
#include <cuda_runtime.h>
#include <cuda_fp16.h>
#include <cstdint>

#define NPTS   200000
#define KK     125
#define NTILES 1563

// smem layout (byte offsets into dynamic smem)
#define A0OFF 1024
#define A1OFF 35840
#define B0OFF 70656
#define B1OFF 140288
#define XOFF  140288
#define WOFF  1024
#define SMEM_BYTES 209920
#define ASTRIDE 272
#define WSTRIDE 528

// ---------- PTX helpers ----------
__device__ __forceinline__ uint32_t smem_u32(const void* p){
    uint32_t a; asm("{ .reg .u64 t; cvta.to.shared.u64 t, %1; cvt.u32.u64 %0, t; }":"=r"(a):"l"(p)); return a;
}
#define CP_ASYNC16(dst,src) asm volatile("cp.async.cg.shared.global [%0], [%1], 16;"::"r"(dst),"l"(src):"memory")
#define CP_COMMIT() asm volatile("cp.async.commit_group;":::"memory")
#define CP_WAIT0()  asm volatile("cp.async.wait_group 0;":::"memory")
#define LDM_X4(r0,r1,r2,r3,a) asm volatile("ldmatrix.sync.aligned.m8n8.x4.shared.b16 {%0,%1,%2,%3}, [%4];" \
    :"=r"(r0),"=r"(r1),"=r"(r2),"=r"(r3):"r"(a))
#define MMA16816(d,a0,a1,a2,a3,b0,b1) asm volatile( \
    "mma.sync.aligned.m16n8k16.row.col.f32.f16.f16.f32 {%0,%1,%2,%3}, {%4,%5,%6,%7}, {%8,%9}, {%0,%1,%2,%3};" \
    :"+f"((d)[0]),"+f"((d)[1]),"+f"((d)[2]),"+f"((d)[3]) \
    :"r"(a0),"r"(a1),"r"(a2),"r"(a3),"r"(b0),"r"(b1))

// ---------- device scratch ----------
__device__ __align__(256) __half g_fh[(size_t)(NPTS+1)*128];           // fp16 feats + zero pad row
__device__ __align__(256) __half g_wimg[(size_t)KK*34816];             // per tap: 256 rows x 136 halves (272B)
__device__ __align__(256) __half g_mimg[(size_t)3*67584];              // per layer: 256 rows x 264 halves (528B)
__device__ int g_kflag[KK];
__device__ int g_act[KK];
__device__ int g_nact;

// ---------- prep ----------
__global__ void prep_feats(const float* __restrict__ f){
    int e = blockIdx.x*256 + threadIdx.x;
    if (e >= (NPTS+1)*128) return;
    float v = (e < NPTS*128) ? f[e] : 0.f;
    g_fh[e] = __float2half_rn(v);
}
__global__ void prep_wm(const float* __restrict__ Wm){
    int e = blockIdx.x*256 + threadIdx.x;
    if (e >= KK*128*256) return;
    int k = e >> 15, c = (e >> 8) & 127, n = e & 255;
    g_wimg[(size_t)k*34816 + n*136 + c] = __float2half_rn(Wm[e]);
}
__global__ void prep_flag(const float* __restrict__ Wm){
    int k = blockIdx.x, t = threadIdx.x, any = 0;
    const float* w = Wm + (size_t)k*32768;
    for (int i=t;i<32768;i+=256) any |= (w[i]!=0.f);
    any = __syncthreads_or(any);
    if (t==0) g_kflag[k] = any;
}
__global__ void prep_compact(){
    int c = 0;
    for (int k=0;k<KK;k++) if (g_kflag[k]) g_act[c++] = k;
    g_nact = c;
}
__global__ void prep_mlp(const float* __restrict__ W0,const float* __restrict__ W1,const float* __restrict__ W2){
    int e = blockIdx.x*256 + threadIdx.x;
    if (e >= 3*65536) return;
    int L = e >> 16, rr = e & 65535, c = rr >> 8, n = rr & 255;
    const float* W = (L==0)?W0:(L==1)?W1:W2;
    g_mimg[(size_t)L*67584 + n*264 + c] = __float2half_rn(W[rr]);
}

// ---------- mma over one [128 x 256] += A[128 x K] * Bt[256 x K]^T tile ----------
template<int STRIDE, int KCHUNKS>
__device__ __forceinline__ void mma_tile(float (&acc)[32][4], uint32_t a_lane, uint32_t b_lane){
    #pragma unroll
    for (int kc = 0; kc < KCHUNKS; kc++){
        uint32_t a0,a1,a2,a3;
        LDM_X4(a0,a1,a2,a3, a_lane + kc*32);
        #pragma unroll
        for (int nt2 = 0; nt2 < 16; nt2++){
            uint32_t b0,b1,b2,b3;
            LDM_X4(b0,b1,b2,b3, b_lane + nt2*16*STRIDE + kc*32);
            MMA16816(acc[2*nt2],   a0,a1,a2,a3, b0,b1);
            MMA16816(acc[2*nt2+1], a0,a1,a2,a3, b2,b3);
        }
    }
}

// ---------- main fused kernel ----------
__global__ void __launch_bounds__(256,1)
ctx_main(const int* __restrict__ neigh, const float* __restrict__ bm,
         const float* __restrict__ b0, const float* __restrict__ b1,
         const float* __restrict__ b2, float* __restrict__ out)
{
    extern __shared__ char smem[];
    const uint32_t sb = smem_u32(smem);
    const int tid = threadIdx.x, w = tid >> 5, l = tid & 31;
    const int nact = g_nact;
    const int tile0 = blockIdx.x * 128;

    float acc[32][4];
    #pragma unroll
    for (int i=0;i<32;i++){ acc[i][0]=0.f; acc[i][1]=0.f; acc[i][2]=0.f; acc[i][3]=0.f; }

    // lane addresses for ldmatrix (per buffer computed by adding buffer offsets)
    const uint32_t aoffl = (uint32_t)((w*16 + (l & 15)) * ASTRIDE + ((l >> 4) << 4));
    const uint32_t boffl = (uint32_t)(((((l >> 4) << 3) + (l & 7)) * ASTRIDE) + (((l >> 3) & 1) << 4));
    const uint32_t xoffl = (uint32_t)((w*16 + (l & 15)) * WSTRIDE + ((l >> 4) << 4));
    const uint32_t woffl = (uint32_t)(((((l >> 4) << 3) + (l & 7)) * WSTRIDE) + (((l >> 3) & 1) << 4));

    const int grow = tid >> 1;           // gather row 0..127
    const int ghs  = tid & 1;            // which 128B half of the row
    const int gp   = tile0 + grow;

    // ---- issue tap 0 ----
    {
        int k = g_act[0];
        int idx = (gp < NPTS) ? __ldg(neigh + (size_t)gp*KK + k) : NPTS;
        const __half* src = g_fh + (size_t)idx*128 + ghs*64;
        uint32_t dst = sb + A0OFF + grow*ASTRIDE + ghs*128;
        #pragma unroll
        for (int i=0;i<8;i++) CP_ASYNC16(dst + i*16, src + i*8);
        const __half* wsrc = g_wimg + (size_t)k*34816;
        #pragma unroll
        for (int i=0;i<17;i++){ int j = tid + i*256; CP_ASYNC16(sb + B0OFF + j*16, wsrc + j*8); }
        CP_COMMIT();
    }

    // ---- ctx taps ----
    for (int a = 0; a < nact; a++){
        CP_WAIT0();
        __syncthreads();
        if (a + 1 < nact){
            int k = g_act[a+1];
            int buf = (a+1) & 1;
            int idx = (gp < NPTS) ? __ldg(neigh + (size_t)gp*KK + k) : NPTS;
            const __half* src = g_fh + (size_t)idx*128 + ghs*64;
            uint32_t dst = sb + (buf ? A1OFF : A0OFF) + grow*ASTRIDE + ghs*128;
            #pragma unroll
            for (int i=0;i<8;i++) CP_ASYNC16(dst + i*16, src + i*8);
            const __half* wsrc = g_wimg + (size_t)k*34816;
            uint32_t bdst = sb + (buf ? B1OFF : B0OFF);
            #pragma unroll
            for (int i=0;i<17;i++){ int j = tid + i*256; CP_ASYNC16(bdst + j*16, wsrc + j*8); }
            CP_COMMIT();
        }
        int buf = a & 1;
        mma_tile<ASTRIDE, 8>(acc, sb + (buf ? A1OFF : A0OFF) + aoffl,
                                  sb + (buf ? B1OFF : B0OFF) + boffl);
    }

    // ---- MLP layers ----
    for (int L = 0; L < 3; L++){
        __syncthreads();   // previous compute done: X/W regions free
        // stream W_L into WOFF
        {
            const __half* wsrc = g_mimg + (size_t)L*67584;
            #pragma unroll
            for (int i=0;i<33;i++){ int j = tid + i*256; CP_ASYNC16(sb + WOFF + j*16, wsrc + j*8); }
            CP_COMMIT();
        }
        // write X = acc + bias_in (relu for L>0), fp16, into XOFF
        const float* biasL = (L==0) ? bm : (L==1) ? b0 : b1;
        #pragma unroll
        for (int nt = 0; nt < 32; nt++){
            int c = nt*8 + (l & 3)*2;
            float bi0 = __ldg(biasL + c), bi1 = __ldg(biasL + c + 1);
            #pragma unroll
            for (int i2 = 0; i2 < 2; i2++){
                int row = w*16 + (l >> 2) + i2*8;
                float v0 = acc[nt][i2*2]   + bi0;
                float v1 = acc[nt][i2*2+1] + bi1;
                if (L){ v0 = fmaxf(v0, 0.f); v1 = fmaxf(v1, 0.f); }
                *(__half2*)(smem + XOFF + row*WSTRIDE + c*2) = __floats2half2_rn(v0, v1);
            }
        }
        #pragma unroll
        for (int i=0;i<32;i++){ acc[i][0]=0.f; acc[i][1]=0.f; acc[i][2]=0.f; acc[i][3]=0.f; }
        CP_WAIT0();
        __syncthreads();
        mma_tile<WSTRIDE, 16>(acc, sb + XOFF + xoffl, sb + WOFF + woffl);
    }

    // ---- final: out = acc + b2; loc = cols<128, scale = |cols>=128| ----
    #pragma unroll
    for (int nt = 0; nt < 32; nt++){
        int c = nt*8 + (l & 3)*2;
        float bi0 = __ldg(b2 + c), bi1 = __ldg(b2 + c + 1);
        #pragma unroll
        for (int i2 = 0; i2 < 2; i2++){
            int row = w*16 + (l >> 2) + i2*8;
            int p = tile0 + row;
            if (p < NPTS){
                float v0 = acc[nt][i2*2]   + bi0;
                float v1 = acc[nt][i2*2+1] + bi1;
                if (c < 128){
                    out[(size_t)p*128 + c]     = v0;
                    out[(size_t)p*128 + c + 1] = v1;
                } else {
                    out[(size_t)NPTS*128 + (size_t)p*128 + (c-128)]     = fabsf(v0);
                    out[(size_t)NPTS*128 + (size_t)p*128 + (c-128) + 1] = fabsf(v1);
                }
            }
        }
    }
}

extern "C" void kernel_launch(void* const* d_in, const int* in_sizes, int n_in,
                              void* d_out, int out_size)
{
    const float* feats = (const float*)d_in[0];
    const int*   neigh = (const int*)d_in[1];
    const float* Wm    = (const float*)d_in[2];
    const float* bm    = (const float*)d_in[3];
    const float* W0    = (const float*)d_in[4];
    const float* b0    = (const float*)d_in[5];
    const float* W1    = (const float*)d_in[6];
    const float* b1    = (const float*)d_in[7];
    const float* W2    = (const float*)d_in[8];
    const float* b2    = (const float*)d_in[9];
    float* out = (float*)d_out;

    static bool cfg = false;
    if (!cfg){
        cudaFuncSetAttribute(ctx_main, cudaFuncAttributeMaxDynamicSharedMemorySize, SMEM_BYTES);
        cfg = true;
    }

    prep_feats<<<((NPTS+1)*128 + 255)/256, 256>>>(feats);
    prep_wm<<<(KK*128*256 + 255)/256, 256>>>(Wm);
    prep_flag<<<KK, 256>>>(Wm);
    prep_compact<<<1,1>>>();
    prep_mlp<<<(3*65536 + 255)/256, 256>>>(W0, W1, W2);
    ctx_main<<<NTILES, 256, SMEM_BYTES>>>(neigh, bm, b0, b1, b2, out);
}

// round 4
// speedup vs baseline: 1.3142x; 1.3142x over previous
#include <cuda_runtime.h>
#include <cuda_fp16.h>
#include <cstdint>

#define NPTS   200000
#define KK     125
#define NTILES 1563

// smem layout (byte offsets into dynamic smem)
#define A0OFF 1024
#define A1OFF 35840
#define B0OFF 70656
#define B1OFF 140288
#define XOFF  140288
#define WOFF  1024
#define SMEM_BYTES 209920
#define ASTRIDE 272
#define WSTRIDE 528

// ---------- PTX helpers ----------
__device__ __forceinline__ uint32_t smem_u32(const void* p){
    uint32_t a; asm("{ .reg .u64 t; cvta.to.shared.u64 t, %1; cvt.u32.u64 %0, t; }":"=r"(a):"l"(p)); return a;
}
#define CP_ASYNC16(dst,src) asm volatile("cp.async.cg.shared.global [%0], [%1], 16;"::"r"(dst),"l"(src):"memory")
#define CP_COMMIT() asm volatile("cp.async.commit_group;":::"memory")
#define CP_WAIT0()  asm volatile("cp.async.wait_group 0;":::"memory")
#define LDM_X4(r0,r1,r2,r3,a) asm volatile("ldmatrix.sync.aligned.m8n8.x4.shared.b16 {%0,%1,%2,%3}, [%4];" \
    :"=r"(r0),"=r"(r1),"=r"(r2),"=r"(r3):"r"(a))
#define MMA16816(d,a0,a1,a2,a3,b0,b1) asm volatile( \
    "mma.sync.aligned.m16n8k16.row.col.f32.f16.f16.f32 {%0,%1,%2,%3}, {%4,%5,%6,%7}, {%8,%9}, {%0,%1,%2,%3};" \
    :"+f"((d)[0]),"+f"((d)[1]),"+f"((d)[2]),"+f"((d)[3]) \
    :"r"(a0),"r"(a1),"r"(a2),"r"(a3),"r"(b0),"r"(b1))

// ---------- device scratch ----------
__device__ __align__(256) __half g_fh[(size_t)(NPTS+1)*128];           // fp16 feats + zero pad row
__device__ __align__(256) __half g_wimg[(size_t)KK*34816];             // per tap: 256 rows x 136 halves (272B)
__device__ __align__(256) __half g_mimg[(size_t)3*67584];              // per layer: 256 rows x 264 halves (528B)
__device__ int g_kflag[KK];
__device__ int g_act[KK];
__device__ int g_nact;

// ---------- prep ----------
__global__ void prep_feats(const float* __restrict__ f){
    int e = blockIdx.x*256 + threadIdx.x;
    if (e >= (NPTS+1)*128) return;
    float v = (e < NPTS*128) ? f[e] : 0.f;
    g_fh[e] = __float2half_rn(v);
}
__global__ void prep_wm(const float* __restrict__ Wm){
    int e = blockIdx.x*256 + threadIdx.x;
    if (e >= KK*128*256) return;
    int k = e >> 15, c = (e >> 8) & 127, n = e & 255;
    g_wimg[(size_t)k*34816 + n*136 + c] = __float2half_rn(Wm[e]);
}
__global__ void prep_flag(const float* __restrict__ Wm){
    int k = blockIdx.x, t = threadIdx.x, any = 0;
    const float* w = Wm + (size_t)k*32768;
    for (int i=t;i<32768;i+=256) any |= (w[i]!=0.f);
    any = __syncthreads_or(any);
    if (t==0) g_kflag[k] = any;
}
__global__ void prep_compact(){
    int c = 0;
    for (int k=0;k<KK;k++) if (g_kflag[k]) g_act[c++] = k;
    g_nact = c;
}
__global__ void prep_mlp(const float* __restrict__ W0,const float* __restrict__ W1,const float* __restrict__ W2){
    int e = blockIdx.x*256 + threadIdx.x;
    if (e >= 3*65536) return;
    int L = e >> 16, rr = e & 65535, c = rr >> 8, n = rr & 255;
    const float* W = (L==0)?W0:(L==1)?W1:W2;
    g_mimg[(size_t)L*67584 + n*264 + c] = __float2half_rn(W[rr]);
}

// ---------- warp-tile MMA: 32(M) x 64(N), K = KC*16 ----------
// Ab = Abase + m0*S + aoff ; Bb = Bbase + n0*S + boff
template<int S, int KC>
__device__ __forceinline__ void mma_tile(float (&acc)[16][4], uint32_t Ab, uint32_t Bb){
    #pragma unroll
    for (int kc = 0; kc < KC; kc++){
        uint32_t a0[4], a1[4];
        LDM_X4(a0[0],a0[1],a0[2],a0[3], Ab + kc*32);
        LDM_X4(a1[0],a1[1],a1[2],a1[3], Ab + 16*S + kc*32);
        #pragma unroll
        for (int nt = 0; nt < 4; nt++){
            uint32_t b0,b1,b2,b3;
            LDM_X4(b0,b1,b2,b3, Bb + nt*16*S + kc*32);
            MMA16816(acc[nt*2],     a0[0],a0[1],a0[2],a0[3], b0,b1);
            MMA16816(acc[nt*2+1],   a0[0],a0[1],a0[2],a0[3], b2,b3);
            MMA16816(acc[8+nt*2],   a1[0],a1[1],a1[2],a1[3], b0,b1);
            MMA16816(acc[8+nt*2+1], a1[0],a1[1],a1[2],a1[3], b2,b3);
        }
    }
}

// ---------- main fused kernel ----------
__global__ void __launch_bounds__(512,1)
ctx_main(const int* __restrict__ neigh, const float* __restrict__ bm,
         const float* __restrict__ b0, const float* __restrict__ b1,
         const float* __restrict__ b2, float* __restrict__ out)
{
    extern __shared__ char smem[];
    const uint32_t sb = smem_u32(smem);
    const int tid = threadIdx.x, wid = tid >> 5, l = tid & 31;
    const int nact = g_nact;
    const int tile0 = blockIdx.x * 128;

    // warp grid: 4 (M) x 4 (N)
    const int m0 = (wid & 3) * 32;
    const int n0 = (wid >> 2) * 64;

    float acc[16][4];
    #pragma unroll
    for (int i=0;i<16;i++){ acc[i][0]=0.f; acc[i][1]=0.f; acc[i][2]=0.f; acc[i][3]=0.f; }

    // ldmatrix lane offsets
    const uint32_t aoffA = (uint32_t)((l & 15) * ASTRIDE + ((l >> 4) << 4));
    const uint32_t boffA = (uint32_t)(((((l >> 4) << 3) | (l & 7)) * ASTRIDE) + (((l >> 3) & 1) << 4));
    const uint32_t aoffW = (uint32_t)((l & 15) * WSTRIDE + ((l >> 4) << 4));
    const uint32_t boffW = (uint32_t)(((((l >> 4) << 3) | (l & 7)) * WSTRIDE) + (((l >> 3) & 1) << 4));

    const int grow = tid >> 2;           // gather row 0..127
    const int gq   = tid & 3;            // quarter of the 256B row
    const int gp   = tile0 + grow;

    // ---- issue tap 0 ----
    {
        int k = g_act[0];
        int idx = (gp < NPTS) ? __ldg(neigh + (size_t)gp*KK + k) : NPTS;
        const __half* src = g_fh + (size_t)idx*128 + gq*32;
        uint32_t dst = sb + A0OFF + grow*ASTRIDE + gq*64;
        #pragma unroll
        for (int i=0;i<4;i++) CP_ASYNC16(dst + i*16, src + i*8);
        const __half* wsrc = g_wimg + (size_t)k*34816;
        #pragma unroll
        for (int i=0;i<9;i++){ int j = tid + i*512; if (j < 4352) CP_ASYNC16(sb + B0OFF + j*16, wsrc + j*8); }
        CP_COMMIT();
    }

    // ---- ctx taps ----
    for (int a = 0; a < nact; a++){
        CP_WAIT0();
        __syncthreads();
        if (a + 1 < nact){
            int k = g_act[a+1];
            int buf = (a+1) & 1;
            int idx = (gp < NPTS) ? __ldg(neigh + (size_t)gp*KK + k) : NPTS;
            const __half* src = g_fh + (size_t)idx*128 + gq*32;
            uint32_t dst = sb + (buf ? A1OFF : A0OFF) + grow*ASTRIDE + gq*64;
            #pragma unroll
            for (int i=0;i<4;i++) CP_ASYNC16(dst + i*16, src + i*8);
            const __half* wsrc = g_wimg + (size_t)k*34816;
            uint32_t bdst = sb + (buf ? B1OFF : B0OFF);
            #pragma unroll
            for (int i=0;i<9;i++){ int j = tid + i*512; if (j < 4352) CP_ASYNC16(bdst + j*16, wsrc + j*8); }
            CP_COMMIT();
        }
        int buf = a & 1;
        uint32_t Ab = sb + (buf ? A1OFF : A0OFF) + m0*ASTRIDE + aoffA;
        uint32_t Bb = sb + (buf ? B1OFF : B0OFF) + n0*ASTRIDE + boffA;
        mma_tile<ASTRIDE, 8>(acc, Ab, Bb);
    }

    // ---- MLP layers ----
    for (int L = 0; L < 3; L++){
        __syncthreads();   // previous compute done: X/W regions free
        // stream W_L into WOFF
        {
            const __half* wsrc = g_mimg + (size_t)L*67584;
            #pragma unroll
            for (int i=0;i<17;i++){ int j = tid + i*512; if (j < 8448) CP_ASYNC16(sb + WOFF + j*16, wsrc + j*8); }
            CP_COMMIT();
        }
        // write X = acc + bias_in (relu for L>0), fp16, into XOFF
        const float* biasL = (L==0) ? bm : (L==1) ? b0 : b1;
        #pragma unroll
        for (int t = 0; t < 16; t++){
            int mt = t >> 3, nt = t & 7;
            int c = n0 + nt*8 + (l & 3)*2;
            float bi0 = __ldg(biasL + c), bi1 = __ldg(biasL + c + 1);
            int r = m0 + mt*16 + (l >> 2);
            float v0 = acc[t][0] + bi0, v1 = acc[t][1] + bi1;
            float v2 = acc[t][2] + bi0, v3 = acc[t][3] + bi1;
            if (L){ v0=fmaxf(v0,0.f); v1=fmaxf(v1,0.f); v2=fmaxf(v2,0.f); v3=fmaxf(v3,0.f); }
            *(__half2*)(smem + XOFF + r*WSTRIDE + c*2)     = __floats2half2_rn(v0, v1);
            *(__half2*)(smem + XOFF + (r+8)*WSTRIDE + c*2) = __floats2half2_rn(v2, v3);
        }
        #pragma unroll
        for (int i=0;i<16;i++){ acc[i][0]=0.f; acc[i][1]=0.f; acc[i][2]=0.f; acc[i][3]=0.f; }
        CP_WAIT0();
        __syncthreads();
        uint32_t Ab = sb + XOFF + m0*WSTRIDE + aoffW;
        uint32_t Bb = sb + WOFF + n0*WSTRIDE + boffW;
        mma_tile<WSTRIDE, 16>(acc, Ab, Bb);
    }

    // ---- final: out = acc + b2; loc = cols<128, scale = |cols>=128| ----
    #pragma unroll
    for (int t = 0; t < 16; t++){
        int mt = t >> 3, nt = t & 7;
        int c = n0 + nt*8 + (l & 3)*2;
        float bi0 = __ldg(b2 + c), bi1 = __ldg(b2 + c + 1);
        #pragma unroll
        for (int h = 0; h < 2; h++){
            int r = m0 + mt*16 + (l >> 2) + h*8;
            int p = tile0 + r;
            if (p < NPTS){
                float v0 = acc[t][h*2]   + bi0;
                float v1 = acc[t][h*2+1] + bi1;
                if (c < 128){
                    out[(size_t)p*128 + c]     = v0;
                    out[(size_t)p*128 + c + 1] = v1;
                } else {
                    out[(size_t)NPTS*128 + (size_t)p*128 + (c-128)]     = fabsf(v0);
                    out[(size_t)NPTS*128 + (size_t)p*128 + (c-128) + 1] = fabsf(v1);
                }
            }
        }
    }
}

extern "C" void kernel_launch(void* const* d_in, const int* in_sizes, int n_in,
                              void* d_out, int out_size)
{
    const float* feats = (const float*)d_in[0];
    const int*   neigh = (const int*)d_in[1];
    const float* Wm    = (const float*)d_in[2];
    const float* bm    = (const float*)d_in[3];
    const float* W0    = (const float*)d_in[4];
    const float* b0    = (const float*)d_in[5];
    const float* W1    = (const float*)d_in[6];
    const float* b1    = (const float*)d_in[7];
    const float* W2    = (const float*)d_in[8];
    const float* b2    = (const float*)d_in[9];
    float* out = (float*)d_out;

    static bool cfg = false;
    if (!cfg){
        cudaFuncSetAttribute(ctx_main, cudaFuncAttributeMaxDynamicSharedMemorySize, SMEM_BYTES);
        cfg = true;
    }

    prep_feats<<<((NPTS+1)*128 + 255)/256, 256>>>(feats);
    prep_wm<<<(KK*128*256 + 255)/256, 256>>>(Wm);
    prep_flag<<<KK, 256>>>(Wm);
    prep_compact<<<1,1>>>();
    prep_mlp<<<(3*65536 + 255)/256, 256>>>(W0, W1, W2);
    ctx_main<<<NTILES, 512, SMEM_BYTES>>>(neigh, bm, b0, b1, b2, out);
}